// round 15
// baseline (speedup 1.0000x reference)
#include <cuda_runtime.h>
#include <cuda_bf16.h>
#include <math.h>
#include <stdint.h>

#define B_SZ   2
#define S_LEN  2048
#define DMODEL 2048
#define NH     16
#define NKV    4
#define HDIM   128
#define GQA    (NH / NKV)
#define MTOT   (B_SZ * S_LEN)           // 4096
#define NQKV   ((NH + 2 * NKV) * HDIM)  // 3072

// ---------------- scratch (allocation-free) ----------------
__device__ __nv_bfloat16 g_xhi[(size_t)MTOT * DMODEL];
__device__ __nv_bfloat16 g_xlo[(size_t)MTOT * DMODEL];
__device__ __nv_bfloat16 g_whi[(size_t)NQKV * DMODEL];
__device__ __nv_bfloat16 g_wlo[(size_t)NQKV * DMODEL];
__device__ __nv_bfloat16 g_wohi[(size_t)DMODEL * DMODEL];
__device__ __nv_bfloat16 g_wolo[(size_t)DMODEL * DMODEL];
__device__ float g_c[(size_t)MTOT * NQKV];
__device__ __nv_bfloat16 g_qh[(size_t)B_SZ * NH  * S_LEN * HDIM];
__device__ __nv_bfloat16 g_ql[(size_t)B_SZ * NH  * S_LEN * HDIM];
__device__ __nv_bfloat16 g_kh[(size_t)B_SZ * NKV * S_LEN * HDIM];
__device__ __nv_bfloat16 g_kl[(size_t)B_SZ * NKV * S_LEN * HDIM];
__device__ __nv_bfloat16 g_vh[(size_t)B_SZ * NKV * HDIM * S_LEN];
__device__ __nv_bfloat16 g_vl[(size_t)B_SZ * NKV * HDIM * S_LEN];
__device__ __nv_bfloat16 g_ohi[(size_t)MTOT * DMODEL];
__device__ __nv_bfloat16 g_olo[(size_t)MTOT * DMODEL];

// ---------------- helpers ----------------
__device__ __forceinline__ uint32_t smem_u32(const void* p) {
    uint32_t a;
    asm("{ .reg .u64 t; cvta.to.shared.u64 t, %1; cvt.u32.u64 %0, t; }" : "=r"(a) : "l"(p));
    return a;
}
__device__ __forceinline__ void cpa16(uint32_t dst, const void* src) {
    asm volatile("cp.async.cg.shared.global [%0], [%1], 16;\n" :: "r"(dst), "l"(src) : "memory");
}
#define CP_COMMIT() asm volatile("cp.async.commit_group;\n" ::: "memory")
#define CP_WAIT(n)  asm volatile("cp.async.wait_group %0;\n" :: "n"(n) : "memory")

__device__ __forceinline__ void ldm_x4(uint32_t& r0, uint32_t& r1, uint32_t& r2, uint32_t& r3,
                                       uint32_t addr) {
    asm volatile("ldmatrix.sync.aligned.m8n8.x4.shared.b16 {%0,%1,%2,%3}, [%4];"
                 : "=r"(r0), "=r"(r1), "=r"(r2), "=r"(r3) : "r"(addr));
}
__device__ __forceinline__ void mma_bf16(float& c0, float& c1, float& c2, float& c3,
                                         uint32_t a0, uint32_t a1, uint32_t a2, uint32_t a3,
                                         uint32_t b0, uint32_t b1) {
    asm volatile(
        "mma.sync.aligned.m16n8k16.row.col.f32.bf16.bf16.f32 "
        "{%0,%1,%2,%3}, {%4,%5,%6,%7}, {%8,%9}, {%0,%1,%2,%3};"
        : "+f"(c0), "+f"(c1), "+f"(c2), "+f"(c3)
        : "r"(a0), "r"(a1), "r"(a2), "r"(a3), "r"(b0), "r"(b1));
}
__device__ __forceinline__ uint32_t pack_bf16(float a, float b) {
    __nv_bfloat162 h = __floats2bfloat162_rn(a, b);
    return *(uint32_t*)&h;
}

// ---------------- fp32 -> bf16 hi/lo split (vectorized) ----------------
__global__ void convert_split2(const float2* __restrict__ src,
                               __nv_bfloat162* __restrict__ hi,
                               __nv_bfloat162* __restrict__ lo, int n2)
{
    int i = blockIdx.x * blockDim.x + threadIdx.x;
    if (i >= n2) return;
    float2 v = src[i];
    __nv_bfloat162 h = __floats2bfloat162_rn(v.x, v.y);
    hi[i] = h;
    lo[i] = __floats2bfloat162_rn(v.x - __bfloat162float(h.x),
                                  v.y - __bfloat162float(h.y));
}

// ---------------- fused split-bf16 mma.sync GEMM (BM=128, BN=256) ----------------
// C[M,N] = (Ahi+Alo)[M,2048] @ (Bhi+Blo)[N,2048]^T, fp32 out.
// BK=32, 4 planes/stage (Ahi|Alo|Bhi|Blo), 2-stage ring, compute-then-prefetch.
// 512 threads = 16 warps (4m x 4n), warp tile 32x64 (R7's verified per-warp shape:
// 12 ldmatrix -> 48 MMAs per k16). j2-blocked B keeps regs ~115.
// 2x MMAs per barrier window vs R7; A-side L2 tile traffic halved.
#define FG_NCH    64                       // 2048 / 32
#define FG_SROW   40                       // bf16 elems per row (80 B)
#define FG_APL    (128 * FG_SROW * 2)      // 10240 B per A plane
#define FG_BPL    (256 * FG_SROW * 2)      // 20480 B per B plane
#define FG_STAGEB (2 * FG_APL + 2 * FG_BPL) // 61440 B
#define FG_SMEM   (2 * FG_STAGEB)          // 122880 B

__global__ void __launch_bounds__(512) hmma_gemm_fused(
    const __nv_bfloat16* __restrict__ Ahi, const __nv_bfloat16* __restrict__ Alo,
    const __nv_bfloat16* __restrict__ Bhi, const __nv_bfloat16* __restrict__ Blo,
    float* __restrict__ C, int ldC)
{
    extern __shared__ __align__(16) char smraw[];
    const uint32_t sbase = smem_u32(smraw);

    const int tid  = threadIdx.x;
    const int lane = tid & 31;
    const int wid  = tid >> 5;        // 0..15
    const int wm   = wid & 3;         // m offset wm*32
    const int wn   = wid >> 2;        // n offset wn*64
    const int m0   = blockIdx.y * 128;
    const int n0   = blockIdx.x * 256;

    const __nv_bfloat16* Ahg = Ahi + (size_t)m0 * DMODEL;
    const __nv_bfloat16* Alg = Alo + (size_t)m0 * DMODEL;
    const __nv_bfloat16* Bhg = Bhi + (size_t)n0 * DMODEL;
    const __nv_bfloat16* Blg = Blo + (size_t)n0 * DMODEL;

    uint32_t aoff[2], boff[4];
#pragma unroll
    for (int i = 0; i < 2; i++)
        aoff[i] = (uint32_t)((wm * 32 + i * 16 + (lane & 15)) * FG_SROW + ((lane >> 4) * 8)) * 2;
#pragma unroll
    for (int j2 = 0; j2 < 4; j2++)
        boff[j2] = (uint32_t)((wn * 64 + j2 * 16 + ((lane >> 4) & 1) * 8 + (lane & 7)) * FG_SROW
                              + (((lane >> 3) & 1) * 8)) * 2;

    float acc[2][8][4];
#pragma unroll
    for (int i = 0; i < 2; i++)
#pragma unroll
        for (int j = 0; j < 8; j++)
#pragma unroll
            for (int r = 0; r < 4; r++) acc[i][j][r] = 0.f;

    // cp.async: A planes 512 chunks (1/thread), B planes 1024 chunks (2/thread)
    auto load_chunk = [&](int c, int slot) {
        int k0 = c * 32;
        uint32_t st = sbase + (uint32_t)slot * FG_STAGEB;
        {
            int row = tid >> 2, cc = tid & 3;
            uint32_t off = (uint32_t)(row * FG_SROW * 2 + cc * 16);
            cpa16(st + off, Ahg + (size_t)row * DMODEL + k0 + cc * 8);
            cpa16(st + FG_APL + off, Alg + (size_t)row * DMODEL + k0 + cc * 8);
        }
#pragma unroll
        for (int i = 0; i < 2; i++) {
            int f = i * 512 + tid;
            int row = f >> 2, cc = f & 3;
            uint32_t off = (uint32_t)(row * FG_SROW * 2 + cc * 16);
            cpa16(st + 2 * FG_APL + off, Bhg + (size_t)row * DMODEL + k0 + cc * 8);
            cpa16(st + 2 * FG_APL + FG_BPL + off, Blg + (size_t)row * DMODEL + k0 + cc * 8);
        }
    };

    load_chunk(0, 0);
    CP_COMMIT();
    load_chunk(1, 1);
    CP_COMMIT();

    for (int c = 0; c < FG_NCH; c++) {
        CP_WAIT(1);
        __syncthreads();
        uint32_t st = sbase + (uint32_t)(c & 1) * FG_STAGEB;
#pragma unroll
        for (int kc = 0; kc < 2; kc++) {
            uint32_t ah[2][4], al[2][4];
#pragma unroll
            for (int i = 0; i < 2; i++) {
                ldm_x4(ah[i][0], ah[i][1], ah[i][2], ah[i][3], st + aoff[i] + kc * 32);
                ldm_x4(al[i][0], al[i][1], al[i][2], al[i][3],
                       st + FG_APL + aoff[i] + kc * 32);
            }
            // j2-blocked: only 8 live B registers at a time
#pragma unroll
            for (int j2 = 0; j2 < 4; j2++) {
                uint32_t bh0, bh1, bh2, bh3, bl0, bl1, bl2, bl3;
                ldm_x4(bh0, bh1, bh2, bh3, st + 2 * FG_APL + boff[j2] + kc * 32);
                ldm_x4(bl0, bl1, bl2, bl3, st + 2 * FG_APL + FG_BPL + boff[j2] + kc * 32);
                int j0 = j2 * 2, j1 = j2 * 2 + 1;
#pragma unroll
                for (int i = 0; i < 2; i++) {
                    mma_bf16(acc[i][j0][0], acc[i][j0][1], acc[i][j0][2], acc[i][j0][3],
                             ah[i][0], ah[i][1], ah[i][2], ah[i][3], bh0, bh1);
                    mma_bf16(acc[i][j0][0], acc[i][j0][1], acc[i][j0][2], acc[i][j0][3],
                             ah[i][0], ah[i][1], ah[i][2], ah[i][3], bl0, bl1);
                    mma_bf16(acc[i][j0][0], acc[i][j0][1], acc[i][j0][2], acc[i][j0][3],
                             al[i][0], al[i][1], al[i][2], al[i][3], bh0, bh1);
                    mma_bf16(acc[i][j1][0], acc[i][j1][1], acc[i][j1][2], acc[i][j1][3],
                             ah[i][0], ah[i][1], ah[i][2], ah[i][3], bh2, bh3);
                    mma_bf16(acc[i][j1][0], acc[i][j1][1], acc[i][j1][2], acc[i][j1][3],
                             ah[i][0], ah[i][1], ah[i][2], ah[i][3], bl2, bl3);
                    mma_bf16(acc[i][j1][0], acc[i][j1][1], acc[i][j1][2], acc[i][j1][3],
                             al[i][0], al[i][1], al[i][2], al[i][3], bh2, bh3);
                }
            }
        }
        __syncthreads();
        if (c + 2 < FG_NCH) {
            load_chunk(c + 2, c & 1);
            CP_COMMIT();
        }
    }

    const int qrow = lane >> 2;
    const int qcol = (lane & 3) * 2;
#pragma unroll
    for (int i = 0; i < 2; i++) {
#pragma unroll
        for (int j = 0; j < 8; j++) {
            int row = m0 + wm * 32 + i * 16 + qrow;
            int col = n0 + wn * 64 + j * 8 + qcol;
            *(float2*)&C[(size_t)row * ldC + col] = make_float2(acc[i][j][0], acc[i][j][1]);
            *(float2*)&C[(size_t)(row + 8) * ldC + col] = make_float2(acc[i][j][2], acc[i][j][3]);
        }
    }
}

// ---------------- RoPE -> bf16 hi/lo, natural [B,H,S,D] layout ----------------
__global__ void rope_q(const float* __restrict__ C,
                       __nv_bfloat16* __restrict__ qh, __nv_bfloat16* __restrict__ ql)
{
    int idx = blockIdx.x * blockDim.x + threadIdx.x;
    int d  = idx & 63;
    int s  = (idx >> 6) & (S_LEN - 1);
    int bh = idx >> 17;
    if (bh >= B_SZ * NH) return;
    int b = bh >> 4, h = bh & 15;
    size_t row = (size_t)(b * S_LEN + s) * NQKV + h * HDIM + d;
    float x1 = C[row], x2 = C[row + 64];
    float ang = (float)s * exp2f(-0.20762050593046014f * (float)d);
    float sn, cs; sincosf(ang, &sn, &cs);
    const float scale = 0.088388347648318447f;  // 1/sqrt(128), folded into Q
    float y1 = (x1 * cs - x2 * sn) * scale;
    float y2 = (x2 * cs + x1 * sn) * scale;
    size_t o = ((size_t)bh * S_LEN + s) * HDIM + d;
    __nv_bfloat16 h1 = __float2bfloat16(y1), h2 = __float2bfloat16(y2);
    qh[o] = h1;      ql[o]      = __float2bfloat16(y1 - __bfloat162float(h1));
    qh[o + 64] = h2; ql[o + 64] = __float2bfloat16(y2 - __bfloat162float(h2));
}

__global__ void rope_k(const float* __restrict__ C,
                       __nv_bfloat16* __restrict__ kh, __nv_bfloat16* __restrict__ kl)
{
    int idx = blockIdx.x * blockDim.x + threadIdx.x;
    int d  = idx & 63;
    int s  = (idx >> 6) & (S_LEN - 1);
    int bh = idx >> 17;
    if (bh >= B_SZ * NKV) return;
    int b = bh >> 2, h = bh & 3;
    size_t row = (size_t)(b * S_LEN + s) * NQKV + NH * HDIM + h * HDIM + d;
    float x1 = C[row], x2 = C[row + 64];
    float ang = (float)s * exp2f(-0.20762050593046014f * (float)d);
    float sn, cs; sincosf(ang, &sn, &cs);
    float y1 = x1 * cs - x2 * sn;
    float y2 = x2 * cs + x1 * sn;
    size_t o = ((size_t)bh * S_LEN + s) * HDIM + d;
    __nv_bfloat16 h1 = __float2bfloat16(y1), h2 = __float2bfloat16(y2);
    kh[o] = h1;      kl[o]      = __float2bfloat16(y1 - __bfloat162float(h1));
    kh[o + 64] = h2; kl[o + 64] = __float2bfloat16(y2 - __bfloat162float(h2));
}

// ---------------- V: transpose to d-major [B,KV,D,S] hi/lo ----------------
__global__ void v_tr(const float* __restrict__ C,
                     __nv_bfloat16* __restrict__ vh, __nv_bfloat16* __restrict__ vl)
{
    __shared__ float tile[32][33];
    int bkv = blockIdx.z;
    int d0 = blockIdx.y * 32;
    int s0 = blockIdx.x * 32;
    int b = bkv >> 2, kv = bkv & 3;
    int tx = threadIdx.x & 31, ty = threadIdx.x >> 5;
#pragma unroll
    for (int i = 0; i < 32; i += 8) {
        int s = s0 + ty + i;
        tile[ty + i][tx] =
            C[(size_t)(b * S_LEN + s) * NQKV + (NH + NKV) * HDIM + kv * HDIM + d0 + tx];
    }
    __syncthreads();
#pragma unroll
    for (int i = 0; i < 32; i += 8) {
        int d = d0 + ty + i;
        float v = tile[tx][ty + i];
        __nv_bfloat16 hb = __float2bfloat16(v);
        size_t o = ((size_t)bkv * HDIM + d) * S_LEN + s0 + tx;
        vh[o] = hb;
        vl[o] = __float2bfloat16(v - __bfloat162float(hb));
    }
}

// ---------------- tensor-core causal flash attention (round-5, verified) ----------------
#define AT_QSTR 136
#define AT_KSTR 136
#define AT_VSTR 72
#define AT_QPL  (128 * AT_QSTR * 2)
#define AT_KPL  (64 * AT_KSTR * 2)
#define AT_VPL  (128 * AT_VSTR * 2)
#define AT_STAGE (2 * AT_KPL + 2 * AT_VPL)
#define AT_SM    (2 * AT_QPL + 2 * AT_STAGE)

__global__ void __launch_bounds__(256) attn_mma(
    const __nv_bfloat16* __restrict__ Qh, const __nv_bfloat16* __restrict__ Ql,
    const __nv_bfloat16* __restrict__ Kh, const __nv_bfloat16* __restrict__ Kl,
    const __nv_bfloat16* __restrict__ Vh, const __nv_bfloat16* __restrict__ Vl,
    __nv_bfloat16* __restrict__ Ohi, __nv_bfloat16* __restrict__ Olo)
{
    extern __shared__ __align__(16) char smraw[];
    const uint32_t sbase = smem_u32(smraw);
    const int tid = threadIdx.x, lane = tid & 31, wid = tid >> 5;
    const int g = lane >> 2, t = lane & 3;
    const int qt = 15 - (int)blockIdx.x;
    const int q0 = qt * 128;
    const int bh = blockIdx.y;
    const int b = bh >> 4, h = bh & 15;
    const int kvh = h >> 2;

    const __nv_bfloat16* qhp = Qh + (size_t)bh * S_LEN * HDIM;
    const __nv_bfloat16* qlp = Ql + (size_t)bh * S_LEN * HDIM;
    const __nv_bfloat16* khp = Kh + (size_t)(b * NKV + kvh) * S_LEN * HDIM;
    const __nv_bfloat16* klp = Kl + (size_t)(b * NKV + kvh) * S_LEN * HDIM;
    const __nv_bfloat16* vhp = Vh + (size_t)(b * NKV + kvh) * HDIM * S_LEN;
    const __nv_bfloat16* vlp = Vl + (size_t)(b * NKV + kvh) * HDIM * S_LEN;

    auto load_kv = [&](int jt, int buf) {
        uint32_t base = sbase + 2 * AT_QPL + (uint32_t)buf * AT_STAGE;
        int k0 = jt * 64;
#pragma unroll
        for (int i = 0; i < 16; i++) {
            int f = i * 256 + tid;
            int sel = f >> 10;
            int r = f & 1023;
            if (sel < 2) {
                int row = r >> 4, c = r & 15;
                cpa16(base + sel * AT_KPL + (uint32_t)(row * AT_KSTR + c * 8) * 2,
                      (sel ? klp : khp) + (size_t)(k0 + row) * HDIM + c * 8);
            } else {
                int d = r >> 3, c = r & 7;
                cpa16(base + 2 * AT_KPL + (sel - 2) * AT_VPL +
                          (uint32_t)(d * AT_VSTR + c * 8) * 2,
                      (sel == 2 ? vhp : vlp) + (size_t)d * S_LEN + k0 + c * 8);
            }
        }
    };

#pragma unroll
    for (int i = 0; i < 16; i++) {
        int f = i * 256 + tid;
        int plane = f >> 11;
        int row = (f >> 4) & 127, c = f & 15;
        cpa16(sbase + plane * AT_QPL + (uint32_t)(row * AT_QSTR + c * 8) * 2,
              (plane ? qlp : qhp) + (size_t)(q0 + row) * HDIM + c * 8);
    }
    const int ntiles = 2 * qt + 2;
    load_kv(0, 0);
    CP_COMMIT();
    load_kv(1, 1);
    CP_COMMIT();

    float mrow[2] = {-1e30f, -1e30f};
    float lrow[2] = {0.f, 0.f};
    float o[16][4];
#pragma unroll
    for (int n = 0; n < 16; n++)
#pragma unroll
        for (int r = 0; r < 4; r++) o[n][r] = 0.f;

    for (int jt = 0; jt < ntiles; jt++) {
        CP_WAIT(1);
        __syncthreads();
        const int k0 = jt * 64;
        const bool skip = (k0 > q0 + wid * 16 + 15);
        if (!skip) {
            uint32_t sb = sbase + 2 * AT_QPL + (uint32_t)(jt & 1) * AT_STAGE;
            float sc[8][4];
#pragma unroll
            for (int j = 0; j < 8; j++)
#pragma unroll
                for (int r = 0; r < 4; r++) sc[j][r] = 0.f;

#pragma unroll
            for (int c = 0; c < 8; c++) {
                uint32_t abyte = (uint32_t)((wid * 16 + (lane & 15)) * AT_QSTR +
                                            c * 16 + (lane >> 4) * 8) * 2;
                uint32_t ah[4], al[4];
                ldm_x4(ah[0], ah[1], ah[2], ah[3], sbase + abyte);
                ldm_x4(al[0], al[1], al[2], al[3], sbase + AT_QPL + abyte);
                uint32_t b0h[8], b1h[8], b0l[8], b1l[8];
#pragma unroll
                for (int j2 = 0; j2 < 4; j2++) {
                    uint32_t bbyte = (uint32_t)((j2 * 16 + ((lane >> 4) & 1) * 8 + (lane & 7)) *
                                                    AT_KSTR + c * 16 + ((lane >> 3) & 1) * 8) * 2;
                    uint32_t r0, r1, r2, r3;
                    ldm_x4(r0, r1, r2, r3, sb + bbyte);
                    b0h[j2 * 2] = r0; b1h[j2 * 2] = r1; b0h[j2 * 2 + 1] = r2; b1h[j2 * 2 + 1] = r3;
                    ldm_x4(r0, r1, r2, r3, sb + AT_KPL + bbyte);
                    b0l[j2 * 2] = r0; b1l[j2 * 2] = r1; b0l[j2 * 2 + 1] = r2; b1l[j2 * 2 + 1] = r3;
                }
#pragma unroll
                for (int j = 0; j < 8; j++) {
                    mma_bf16(sc[j][0], sc[j][1], sc[j][2], sc[j][3],
                             ah[0], ah[1], ah[2], ah[3], b0h[j], b1h[j]);
                    mma_bf16(sc[j][0], sc[j][1], sc[j][2], sc[j][3],
                             ah[0], ah[1], ah[2], ah[3], b0l[j], b1l[j]);
                    mma_bf16(sc[j][0], sc[j][1], sc[j][2], sc[j][3],
                             al[0], al[1], al[2], al[3], b0h[j], b1h[j]);
                }
            }

            if (k0 + 63 > q0 + wid * 16) {
#pragma unroll
                for (int j = 0; j < 8; j++)
#pragma unroll
                    for (int r = 0; r < 4; r++) {
                        int col = k0 + j * 8 + t * 2 + (r & 1);
                        int row = q0 + wid * 16 + g + ((r >> 1) * 8);
                        if (col > row) sc[j][r] = -1e30f;
                    }
            }

            float mx0 = -1e30f, mx1 = -1e30f;
#pragma unroll
            for (int j = 0; j < 8; j++) {
                mx0 = fmaxf(mx0, fmaxf(sc[j][0], sc[j][1]));
                mx1 = fmaxf(mx1, fmaxf(sc[j][2], sc[j][3]));
            }
            mx0 = fmaxf(mx0, __shfl_xor_sync(0xffffffffu, mx0, 1));
            mx0 = fmaxf(mx0, __shfl_xor_sync(0xffffffffu, mx0, 2));
            mx1 = fmaxf(mx1, __shfl_xor_sync(0xffffffffu, mx1, 1));
            mx1 = fmaxf(mx1, __shfl_xor_sync(0xffffffffu, mx1, 2));
            float mn0 = fmaxf(mrow[0], mx0), mn1 = fmaxf(mrow[1], mx1);
            float cr0 = __expf(mrow[0] - mn0), cr1 = __expf(mrow[1] - mn1);
            mrow[0] = mn0; mrow[1] = mn1;
            float rs0 = 0.f, rs1 = 0.f;
#pragma unroll
            for (int j = 0; j < 8; j++) {
                sc[j][0] = __expf(sc[j][0] - mn0);
                sc[j][1] = __expf(sc[j][1] - mn0);
                sc[j][2] = __expf(sc[j][2] - mn1);
                sc[j][3] = __expf(sc[j][3] - mn1);
                rs0 += sc[j][0] + sc[j][1];
                rs1 += sc[j][2] + sc[j][3];
            }
            rs0 += __shfl_xor_sync(0xffffffffu, rs0, 1);
            rs0 += __shfl_xor_sync(0xffffffffu, rs0, 2);
            rs1 += __shfl_xor_sync(0xffffffffu, rs1, 1);
            rs1 += __shfl_xor_sync(0xffffffffu, rs1, 2);
            lrow[0] = lrow[0] * cr0 + rs0;
            lrow[1] = lrow[1] * cr1 + rs1;
#pragma unroll
            for (int n = 0; n < 16; n++) {
                o[n][0] *= cr0; o[n][1] *= cr0; o[n][2] *= cr1; o[n][3] *= cr1;
            }

            uint32_t pAh[8], pBh[8], pAl[8], pBl[8];
#pragma unroll
            for (int j = 0; j < 8; j++) {
                pAh[j] = pack_bf16(sc[j][0], sc[j][1]);
                pBh[j] = pack_bf16(sc[j][2], sc[j][3]);
                __nv_bfloat162 hA = *(__nv_bfloat162*)&pAh[j];
                __nv_bfloat162 hB = *(__nv_bfloat162*)&pBh[j];
                pAl[j] = pack_bf16(sc[j][0] - __bfloat162float(hA.x),
                                   sc[j][1] - __bfloat162float(hA.y));
                pBl[j] = pack_bf16(sc[j][2] - __bfloat162float(hB.x),
                                   sc[j][3] - __bfloat162float(hB.y));
            }

#pragma unroll
            for (int c = 0; c < 4; c++) {
                uint32_t vb0h[16], vb1h[16], vb0l[16], vb1l[16];
#pragma unroll
                for (int j2 = 0; j2 < 8; j2++) {
                    uint32_t bbyte = (uint32_t)((j2 * 16 + ((lane >> 4) & 1) * 8 + (lane & 7)) *
                                                    AT_VSTR + c * 16 + ((lane >> 3) & 1) * 8) * 2;
                    uint32_t r0, r1, r2, r3;
                    ldm_x4(r0, r1, r2, r3, sb + 2 * AT_KPL + bbyte);
                    vb0h[j2 * 2] = r0; vb1h[j2 * 2] = r1;
                    vb0h[j2 * 2 + 1] = r2; vb1h[j2 * 2 + 1] = r3;
                    ldm_x4(r0, r1, r2, r3, sb + 2 * AT_KPL + AT_VPL + bbyte);
                    vb0l[j2 * 2] = r0; vb1l[j2 * 2] = r1;
                    vb0l[j2 * 2 + 1] = r2; vb1l[j2 * 2 + 1] = r3;
                }
                uint32_t ah0 = pAh[2 * c], ah1 = pBh[2 * c], ah2 = pAh[2 * c + 1], ah3 = pBh[2 * c + 1];
                uint32_t al0 = pAl[2 * c], al1 = pBl[2 * c], al2 = pAl[2 * c + 1], al3 = pBl[2 * c + 1];
#pragma unroll
                for (int n = 0; n < 16; n++) {
                    mma_bf16(o[n][0], o[n][1], o[n][2], o[n][3],
                             ah0, ah1, ah2, ah3, vb0h[n], vb1h[n]);
                    mma_bf16(o[n][0], o[n][1], o[n][2], o[n][3],
                             ah0, ah1, ah2, ah3, vb0l[n], vb1l[n]);
                    mma_bf16(o[n][0], o[n][1], o[n][2], o[n][3],
                             al0, al1, al2, al3, vb0h[n], vb1h[n]);
                }
            }
        }
        __syncthreads();
        if (jt + 2 < ntiles) {
            load_kv(jt + 2, jt & 1);
            CP_COMMIT();
        }
    }

    float inv0 = 1.f / lrow[0], inv1 = 1.f / lrow[1];
    int row0 = q0 + wid * 16 + g;
#pragma unroll
    for (int n = 0; n < 16; n++) {
        int col = h * HDIM + n * 8 + t * 2;
        float v0 = o[n][0] * inv0, v1 = o[n][1] * inv0;
        float v2 = o[n][2] * inv1, v3 = o[n][3] * inv1;
        __nv_bfloat162 h01 = __floats2bfloat162_rn(v0, v1);
        __nv_bfloat162 l01 = __floats2bfloat162_rn(v0 - __bfloat162float(h01.x),
                                                   v1 - __bfloat162float(h01.y));
        __nv_bfloat162 h23 = __floats2bfloat162_rn(v2, v3);
        __nv_bfloat162 l23 = __floats2bfloat162_rn(v2 - __bfloat162float(h23.x),
                                                   v3 - __bfloat162float(h23.y));
        size_t p0 = (size_t)(b * S_LEN + row0) * DMODEL + col;
        size_t p1 = (size_t)(b * S_LEN + row0 + 8) * DMODEL + col;
        *(__nv_bfloat162*)&Ohi[p0] = h01;
        *(__nv_bfloat162*)&Olo[p0] = l01;
        *(__nv_bfloat162*)&Ohi[p1] = h23;
        *(__nv_bfloat162*)&Olo[p1] = l23;
    }
}

// ---------------------------------------------------------------------------
extern "C" void kernel_launch(void* const* d_in, const int* in_sizes, int n_in,
                              void* d_out, int out_size)
{
    const float* x  = (const float*)d_in[0];
    const float* wq = (const float*)d_in[1];
    const float* wk = (const float*)d_in[2];
    const float* wv = (const float*)d_in[3];
    const float* wo = (const float*)d_in[4];
    float* out = (float*)d_out;

    __nv_bfloat16 *xhi, *xlo, *whi, *wlo, *wohi, *wolo, *ohi, *olo;
    __nv_bfloat16 *qh, *ql, *kh, *kl, *vh, *vl;
    float *c;
    cudaGetSymbolAddress((void**)&xhi,  g_xhi);
    cudaGetSymbolAddress((void**)&xlo,  g_xlo);
    cudaGetSymbolAddress((void**)&whi,  g_whi);
    cudaGetSymbolAddress((void**)&wlo,  g_wlo);
    cudaGetSymbolAddress((void**)&wohi, g_wohi);
    cudaGetSymbolAddress((void**)&wolo, g_wolo);
    cudaGetSymbolAddress((void**)&ohi,  g_ohi);
    cudaGetSymbolAddress((void**)&olo,  g_olo);
    cudaGetSymbolAddress((void**)&c,  g_c);
    cudaGetSymbolAddress((void**)&qh, g_qh);
    cudaGetSymbolAddress((void**)&ql, g_ql);
    cudaGetSymbolAddress((void**)&kh, g_kh);
    cudaGetSymbolAddress((void**)&kl, g_kl);
    cudaGetSymbolAddress((void**)&vh, g_vh);
    cudaGetSymbolAddress((void**)&vl, g_vl);

    convert_split2<<<(MTOT * DMODEL / 2) / 256, 256>>>(
        (const float2*)x, (__nv_bfloat162*)xhi, (__nv_bfloat162*)xlo, MTOT * DMODEL / 2);
    convert_split2<<<(NH * HDIM * DMODEL / 2) / 256, 256>>>(
        (const float2*)wq, (__nv_bfloat162*)whi, (__nv_bfloat162*)wlo, NH * HDIM * DMODEL / 2);
    convert_split2<<<(NKV * HDIM * DMODEL / 2) / 256, 256>>>(
        (const float2*)wk, (__nv_bfloat162*)(whi + (size_t)NH * HDIM * DMODEL),
        (__nv_bfloat162*)(wlo + (size_t)NH * HDIM * DMODEL), NKV * HDIM * DMODEL / 2);
    convert_split2<<<(NKV * HDIM * DMODEL / 2) / 256, 256>>>(
        (const float2*)wv, (__nv_bfloat162*)(whi + (size_t)(NH + NKV) * HDIM * DMODEL),
        (__nv_bfloat162*)(wlo + (size_t)(NH + NKV) * HDIM * DMODEL), NKV * HDIM * DMODEL / 2);
    convert_split2<<<(DMODEL * DMODEL / 2) / 256, 256>>>(
        (const float2*)wo, (__nv_bfloat162*)wohi, (__nv_bfloat162*)wolo, DMODEL * DMODEL / 2);

    cudaFuncSetAttribute(hmma_gemm_fused, cudaFuncAttributeMaxDynamicSharedMemorySize, FG_SMEM);

    // fused QKV projection: C[4096, 3072]
    hmma_gemm_fused<<<dim3(NQKV / 256, MTOT / 128), 512, FG_SMEM>>>(xhi, xlo, whi, wlo, c, NQKV);

    rope_q<<<(B_SZ * NH * S_LEN * 64) / 256, 256>>>(c, qh, ql);
    rope_k<<<(B_SZ * NKV * S_LEN * 64) / 256, 256>>>(c, kh, kl);
    v_tr<<<dim3(S_LEN / 32, HDIM / 32, B_SZ * NKV), 256>>>(c, vh, vl);

    cudaFuncSetAttribute(attn_mma, cudaFuncAttributeMaxDynamicSharedMemorySize, AT_SM);
    attn_mma<<<dim3(S_LEN / 128, B_SZ * NH), 256, AT_SM>>>(qh, ql, kh, kl, vh, vl, ohi, olo);

    hmma_gemm_fused<<<dim3(DMODEL / 256, MTOT / 128), 512, FG_SMEM>>>(ohi, olo, wohi, wolo, out, DMODEL);
}

// round 16
// speedup vs baseline: 1.0405x; 1.0405x over previous
#include <cuda_runtime.h>
#include <cuda_bf16.h>
#include <math.h>
#include <stdint.h>

#define B_SZ   2
#define S_LEN  2048
#define DMODEL 2048
#define NH     16
#define NKV    4
#define HDIM   128
#define GQA    (NH / NKV)
#define MTOT   (B_SZ * S_LEN)           // 4096
#define NQKV   ((NH + 2 * NKV) * HDIM)  // 3072

// ---------------- scratch (allocation-free) ----------------
__device__ __nv_bfloat16 g_xhi[(size_t)MTOT * DMODEL];
__device__ __nv_bfloat16 g_xlo[(size_t)MTOT * DMODEL];
__device__ __nv_bfloat16 g_whi[(size_t)NQKV * DMODEL];
__device__ __nv_bfloat16 g_wlo[(size_t)NQKV * DMODEL];
__device__ __nv_bfloat16 g_wohi[(size_t)DMODEL * DMODEL];
__device__ __nv_bfloat16 g_wolo[(size_t)DMODEL * DMODEL];
__device__ float g_c[(size_t)MTOT * NQKV];
__device__ __nv_bfloat16 g_qh[(size_t)B_SZ * NH  * S_LEN * HDIM];
__device__ __nv_bfloat16 g_ql[(size_t)B_SZ * NH  * S_LEN * HDIM];
__device__ __nv_bfloat16 g_kh[(size_t)B_SZ * NKV * S_LEN * HDIM];
__device__ __nv_bfloat16 g_kl[(size_t)B_SZ * NKV * S_LEN * HDIM];
__device__ __nv_bfloat16 g_vh[(size_t)B_SZ * NKV * HDIM * S_LEN];
__device__ __nv_bfloat16 g_vl[(size_t)B_SZ * NKV * HDIM * S_LEN];
__device__ __nv_bfloat16 g_ohi[(size_t)MTOT * DMODEL];
__device__ __nv_bfloat16 g_olo[(size_t)MTOT * DMODEL];

// ---------------- helpers ----------------
__device__ __forceinline__ uint32_t smem_u32(const void* p) {
    uint32_t a;
    asm("{ .reg .u64 t; cvta.to.shared.u64 t, %1; cvt.u32.u64 %0, t; }" : "=r"(a) : "l"(p));
    return a;
}
__device__ __forceinline__ void cpa16(uint32_t dst, const void* src) {
    asm volatile("cp.async.cg.shared.global [%0], [%1], 16;\n" :: "r"(dst), "l"(src) : "memory");
}
#define CP_COMMIT() asm volatile("cp.async.commit_group;\n" ::: "memory")
#define CP_WAIT(n)  asm volatile("cp.async.wait_group %0;\n" :: "n"(n) : "memory")

__device__ __forceinline__ void ldm_x4(uint32_t& r0, uint32_t& r1, uint32_t& r2, uint32_t& r3,
                                       uint32_t addr) {
    asm volatile("ldmatrix.sync.aligned.m8n8.x4.shared.b16 {%0,%1,%2,%3}, [%4];"
                 : "=r"(r0), "=r"(r1), "=r"(r2), "=r"(r3) : "r"(addr));
}
__device__ __forceinline__ void mma_bf16(float& c0, float& c1, float& c2, float& c3,
                                         uint32_t a0, uint32_t a1, uint32_t a2, uint32_t a3,
                                         uint32_t b0, uint32_t b1) {
    asm volatile(
        "mma.sync.aligned.m16n8k16.row.col.f32.bf16.bf16.f32 "
        "{%0,%1,%2,%3}, {%4,%5,%6,%7}, {%8,%9}, {%0,%1,%2,%3};"
        : "+f"(c0), "+f"(c1), "+f"(c2), "+f"(c3)
        : "r"(a0), "r"(a1), "r"(a2), "r"(a3), "r"(b0), "r"(b1));
}
__device__ __forceinline__ uint32_t pack_bf16(float a, float b) {
    __nv_bfloat162 h = __floats2bfloat162_rn(a, b);
    return *(uint32_t*)&h;
}

// ---------------- fp32 -> bf16 hi/lo split (float4-wide) ----------------
__global__ void convert_split4(const float4* __restrict__ src,
                               __nv_bfloat162* __restrict__ hi,
                               __nv_bfloat162* __restrict__ lo, int n4)
{
    int i = blockIdx.x * blockDim.x + threadIdx.x;
    if (i >= n4) return;
    float4 v = src[i];
    __nv_bfloat162 h0 = __floats2bfloat162_rn(v.x, v.y);
    __nv_bfloat162 h1 = __floats2bfloat162_rn(v.z, v.w);
    hi[i * 2 + 0] = h0;
    hi[i * 2 + 1] = h1;
    lo[i * 2 + 0] = __floats2bfloat162_rn(v.x - __bfloat162float(h0.x),
                                          v.y - __bfloat162float(h0.y));
    lo[i * 2 + 1] = __floats2bfloat162_rn(v.z - __bfloat162float(h1.x),
                                          v.w - __bfloat162float(h1.y));
}

// ---------------- fused split-bf16 mma.sync GEMM (2 CTAs/SM, R13-verified) ----------------
// C[M,N] = (Ahi+Alo)[M,2048] @ (Bhi+Blo)[N,2048]^T, fp32 out.
// BM=BN=128, BK=32, 4 planes/stage, 2-stage ring, compute-then-prefetch.
// 8 warps (4x2), warp tile 32x64, j2-blocked B, __launch_bounds__(256,2).
#define FG_NCH    64                       // 2048 / 32
#define FG_SROW   40                       // bf16 elems per row (80 B)
#define FG_PLANE  (128 * FG_SROW * 2)      // 10240 B
#define FG_STAGEB (4 * FG_PLANE)           // 40960 B
#define FG_SMEM   (2 * FG_STAGEB)          // 81920 B

__global__ void __launch_bounds__(256, 2) hmma_gemm_fused(
    const __nv_bfloat16* __restrict__ Ahi, const __nv_bfloat16* __restrict__ Alo,
    const __nv_bfloat16* __restrict__ Bhi, const __nv_bfloat16* __restrict__ Blo,
    float* __restrict__ C, int ldC)
{
    extern __shared__ __align__(16) char smraw[];
    const uint32_t sbase = smem_u32(smraw);

    const int tid  = threadIdx.x;
    const int lane = tid & 31;
    const int wid  = tid >> 5;
    const int wm   = wid & 3;
    const int wn   = wid >> 2;
    const int m0   = blockIdx.y * 128;
    const int n0   = blockIdx.x * 128;

    const __nv_bfloat16* G[4] = {Ahi + (size_t)m0 * DMODEL, Alo + (size_t)m0 * DMODEL,
                                 Bhi + (size_t)n0 * DMODEL, Blo + (size_t)n0 * DMODEL};

    const int ar0 = tid >> 2, ac0 = tid & 3;
    const int ar1 = (tid + 256) >> 2, ac1 = (tid + 256) & 3;

    uint32_t aoff[2], boff[4];
#pragma unroll
    for (int i = 0; i < 2; i++)
        aoff[i] = (uint32_t)((wm * 32 + i * 16 + (lane & 15)) * FG_SROW + ((lane >> 4) * 8)) * 2;
#pragma unroll
    for (int j2 = 0; j2 < 4; j2++)
        boff[j2] = (uint32_t)((wn * 64 + j2 * 16 + ((lane >> 4) & 1) * 8 + (lane & 7)) * FG_SROW
                              + (((lane >> 3) & 1) * 8)) * 2;

    float acc[2][8][4];
#pragma unroll
    for (int i = 0; i < 2; i++)
#pragma unroll
        for (int j = 0; j < 8; j++)
#pragma unroll
            for (int r = 0; r < 4; r++) acc[i][j][r] = 0.f;

    auto load_chunk = [&](int c, int slot) {
        int k0 = c * 32;
        uint32_t st = sbase + (uint32_t)slot * FG_STAGEB;
#pragma unroll
        for (int p = 0; p < 4; p++) {
            cpa16(st + p * FG_PLANE + (uint32_t)(ar0 * FG_SROW * 2 + ac0 * 16),
                  G[p] + (size_t)ar0 * DMODEL + k0 + ac0 * 8);
            cpa16(st + p * FG_PLANE + (uint32_t)(ar1 * FG_SROW * 2 + ac1 * 16),
                  G[p] + (size_t)ar1 * DMODEL + k0 + ac1 * 8);
        }
    };

    load_chunk(0, 0);
    CP_COMMIT();
    load_chunk(1, 1);
    CP_COMMIT();

    for (int c = 0; c < FG_NCH; c++) {
        CP_WAIT(1);
        __syncthreads();
        uint32_t st = sbase + (uint32_t)(c & 1) * FG_STAGEB;
#pragma unroll
        for (int kc = 0; kc < 2; kc++) {
            uint32_t ah[2][4], al[2][4];
#pragma unroll
            for (int i = 0; i < 2; i++) {
                ldm_x4(ah[i][0], ah[i][1], ah[i][2], ah[i][3], st + aoff[i] + kc * 32);
                ldm_x4(al[i][0], al[i][1], al[i][2], al[i][3],
                       st + FG_PLANE + aoff[i] + kc * 32);
            }
            // j2-blocked: only 8 live B registers at a time
#pragma unroll
            for (int j2 = 0; j2 < 4; j2++) {
                uint32_t bh0, bh1, bh2, bh3, bl0, bl1, bl2, bl3;
                ldm_x4(bh0, bh1, bh2, bh3, st + 2 * FG_PLANE + boff[j2] + kc * 32);
                ldm_x4(bl0, bl1, bl2, bl3, st + 3 * FG_PLANE + boff[j2] + kc * 32);
                int j0 = j2 * 2, j1 = j2 * 2 + 1;
#pragma unroll
                for (int i = 0; i < 2; i++) {
                    mma_bf16(acc[i][j0][0], acc[i][j0][1], acc[i][j0][2], acc[i][j0][3],
                             ah[i][0], ah[i][1], ah[i][2], ah[i][3], bh0, bh1);
                    mma_bf16(acc[i][j0][0], acc[i][j0][1], acc[i][j0][2], acc[i][j0][3],
                             ah[i][0], ah[i][1], ah[i][2], ah[i][3], bl0, bl1);
                    mma_bf16(acc[i][j0][0], acc[i][j0][1], acc[i][j0][2], acc[i][j0][3],
                             al[i][0], al[i][1], al[i][2], al[i][3], bh0, bh1);
                    mma_bf16(acc[i][j1][0], acc[i][j1][1], acc[i][j1][2], acc[i][j1][3],
                             ah[i][0], ah[i][1], ah[i][2], ah[i][3], bh2, bh3);
                    mma_bf16(acc[i][j1][0], acc[i][j1][1], acc[i][j1][2], acc[i][j1][3],
                             ah[i][0], ah[i][1], ah[i][2], ah[i][3], bl2, bl3);
                    mma_bf16(acc[i][j1][0], acc[i][j1][1], acc[i][j1][2], acc[i][j1][3],
                             al[i][0], al[i][1], al[i][2], al[i][3], bh2, bh3);
                }
            }
        }
        __syncthreads();
        if (c + 2 < FG_NCH) {
            load_chunk(c + 2, c & 1);
            CP_COMMIT();
        }
    }

    const int qrow = lane >> 2;
    const int qcol = (lane & 3) * 2;
#pragma unroll
    for (int i = 0; i < 2; i++) {
#pragma unroll
        for (int j = 0; j < 8; j++) {
            int row = m0 + wm * 32 + i * 16 + qrow;
            int col = n0 + wn * 64 + j * 8 + qcol;
            *(float2*)&C[(size_t)row * ldC + col] = make_float2(acc[i][j][0], acc[i][j][1]);
            *(float2*)&C[(size_t)(row + 8) * ldC + col] = make_float2(acc[i][j][2], acc[i][j][3]);
        }
    }
}

// ---------------- fused RoPE (Q and K in one launch) -> bf16 hi/lo ----------------
#define QCOUNT (B_SZ * NH * S_LEN * 64)   // 4,194,304
#define KCOUNT (B_SZ * NKV * S_LEN * 64)  // 1,048,576

__global__ void rope_qk(const float* __restrict__ C,
                        __nv_bfloat16* __restrict__ qh, __nv_bfloat16* __restrict__ ql,
                        __nv_bfloat16* __restrict__ kh, __nv_bfloat16* __restrict__ kl)
{
    int idx = blockIdx.x * blockDim.x + threadIdx.x;
    if (idx < QCOUNT) {
        int d  = idx & 63;
        int s  = (idx >> 6) & (S_LEN - 1);
        int bh = idx >> 17;
        int b = bh >> 4, h = bh & 15;
        size_t row = (size_t)(b * S_LEN + s) * NQKV + h * HDIM + d;
        float x1 = C[row], x2 = C[row + 64];
        float ang = (float)s * exp2f(-0.20762050593046014f * (float)d);
        float sn, cs; sincosf(ang, &sn, &cs);
        const float scale = 0.088388347648318447f;  // 1/sqrt(128), folded into Q
        float y1 = (x1 * cs - x2 * sn) * scale;
        float y2 = (x2 * cs + x1 * sn) * scale;
        size_t o = ((size_t)bh * S_LEN + s) * HDIM + d;
        __nv_bfloat16 h1 = __float2bfloat16(y1), h2 = __float2bfloat16(y2);
        qh[o] = h1;      ql[o]      = __float2bfloat16(y1 - __bfloat162float(h1));
        qh[o + 64] = h2; ql[o + 64] = __float2bfloat16(y2 - __bfloat162float(h2));
    } else {
        int kidx = idx - QCOUNT;
        if (kidx >= KCOUNT) return;
        int d  = kidx & 63;
        int s  = (kidx >> 6) & (S_LEN - 1);
        int bh = kidx >> 17;
        int b = bh >> 2, h = bh & 3;
        size_t row = (size_t)(b * S_LEN + s) * NQKV + NH * HDIM + h * HDIM + d;
        float x1 = C[row], x2 = C[row + 64];
        float ang = (float)s * exp2f(-0.20762050593046014f * (float)d);
        float sn, cs; sincosf(ang, &sn, &cs);
        float y1 = x1 * cs - x2 * sn;
        float y2 = x2 * cs + x1 * sn;
        size_t o = ((size_t)bh * S_LEN + s) * HDIM + d;
        __nv_bfloat16 h1 = __float2bfloat16(y1), h2 = __float2bfloat16(y2);
        kh[o] = h1;      kl[o]      = __float2bfloat16(y1 - __bfloat162float(h1));
        kh[o + 64] = h2; kl[o + 64] = __float2bfloat16(y2 - __bfloat162float(h2));
    }
}

// ---------------- V: transpose to d-major [B,KV,D,S] hi/lo ----------------
__global__ void v_tr(const float* __restrict__ C,
                     __nv_bfloat16* __restrict__ vh, __nv_bfloat16* __restrict__ vl)
{
    __shared__ float tile[32][33];
    int bkv = blockIdx.z;
    int d0 = blockIdx.y * 32;
    int s0 = blockIdx.x * 32;
    int b = bkv >> 2, kv = bkv & 3;
    int tx = threadIdx.x & 31, ty = threadIdx.x >> 5;
#pragma unroll
    for (int i = 0; i < 32; i += 8) {
        int s = s0 + ty + i;
        tile[ty + i][tx] =
            C[(size_t)(b * S_LEN + s) * NQKV + (NH + NKV) * HDIM + kv * HDIM + d0 + tx];
    }
    __syncthreads();
#pragma unroll
    for (int i = 0; i < 32; i += 8) {
        int d = d0 + ty + i;
        float v = tile[tx][ty + i];
        __nv_bfloat16 hb = __float2bfloat16(v);
        size_t o = ((size_t)bkv * HDIM + d) * S_LEN + s0 + tx;
        vh[o] = hb;
        vl[o] = __float2bfloat16(v - __bfloat162float(hb));
    }
}

// ---------------- tensor-core causal flash attention (round-5, verified) ----------------
#define AT_QSTR 136
#define AT_KSTR 136
#define AT_VSTR 72
#define AT_QPL  (128 * AT_QSTR * 2)
#define AT_KPL  (64 * AT_KSTR * 2)
#define AT_VPL  (128 * AT_VSTR * 2)
#define AT_STAGE (2 * AT_KPL + 2 * AT_VPL)
#define AT_SM    (2 * AT_QPL + 2 * AT_STAGE)

__global__ void __launch_bounds__(256) attn_mma(
    const __nv_bfloat16* __restrict__ Qh, const __nv_bfloat16* __restrict__ Ql,
    const __nv_bfloat16* __restrict__ Kh, const __nv_bfloat16* __restrict__ Kl,
    const __nv_bfloat16* __restrict__ Vh, const __nv_bfloat16* __restrict__ Vl,
    __nv_bfloat16* __restrict__ Ohi, __nv_bfloat16* __restrict__ Olo)
{
    extern __shared__ __align__(16) char smraw[];
    const uint32_t sbase = smem_u32(smraw);
    const int tid = threadIdx.x, lane = tid & 31, wid = tid >> 5;
    const int g = lane >> 2, t = lane & 3;
    const int qt = 15 - (int)blockIdx.x;
    const int q0 = qt * 128;
    const int bh = blockIdx.y;
    const int b = bh >> 4, h = bh & 15;
    const int kvh = h >> 2;

    const __nv_bfloat16* qhp = Qh + (size_t)bh * S_LEN * HDIM;
    const __nv_bfloat16* qlp = Ql + (size_t)bh * S_LEN * HDIM;
    const __nv_bfloat16* khp = Kh + (size_t)(b * NKV + kvh) * S_LEN * HDIM;
    const __nv_bfloat16* klp = Kl + (size_t)(b * NKV + kvh) * S_LEN * HDIM;
    const __nv_bfloat16* vhp = Vh + (size_t)(b * NKV + kvh) * HDIM * S_LEN;
    const __nv_bfloat16* vlp = Vl + (size_t)(b * NKV + kvh) * HDIM * S_LEN;

    auto load_kv = [&](int jt, int buf) {
        uint32_t base = sbase + 2 * AT_QPL + (uint32_t)buf * AT_STAGE;
        int k0 = jt * 64;
#pragma unroll
        for (int i = 0; i < 16; i++) {
            int f = i * 256 + tid;
            int sel = f >> 10;
            int r = f & 1023;
            if (sel < 2) {
                int row = r >> 4, c = r & 15;
                cpa16(base + sel * AT_KPL + (uint32_t)(row * AT_KSTR + c * 8) * 2,
                      (sel ? klp : khp) + (size_t)(k0 + row) * HDIM + c * 8);
            } else {
                int d = r >> 3, c = r & 7;
                cpa16(base + 2 * AT_KPL + (sel - 2) * AT_VPL +
                          (uint32_t)(d * AT_VSTR + c * 8) * 2,
                      (sel == 2 ? vhp : vlp) + (size_t)d * S_LEN + k0 + c * 8);
            }
        }
    };

#pragma unroll
    for (int i = 0; i < 16; i++) {
        int f = i * 256 + tid;
        int plane = f >> 11;
        int row = (f >> 4) & 127, c = f & 15;
        cpa16(sbase + plane * AT_QPL + (uint32_t)(row * AT_QSTR + c * 8) * 2,
              (plane ? qlp : qhp) + (size_t)(q0 + row) * HDIM + c * 8);
    }
    const int ntiles = 2 * qt + 2;
    load_kv(0, 0);
    CP_COMMIT();
    load_kv(1, 1);
    CP_COMMIT();

    float mrow[2] = {-1e30f, -1e30f};
    float lrow[2] = {0.f, 0.f};
    float o[16][4];
#pragma unroll
    for (int n = 0; n < 16; n++)
#pragma unroll
        for (int r = 0; r < 4; r++) o[n][r] = 0.f;

    for (int jt = 0; jt < ntiles; jt++) {
        CP_WAIT(1);
        __syncthreads();
        const int k0 = jt * 64;
        const bool skip = (k0 > q0 + wid * 16 + 15);
        if (!skip) {
            uint32_t sb = sbase + 2 * AT_QPL + (uint32_t)(jt & 1) * AT_STAGE;
            float sc[8][4];
#pragma unroll
            for (int j = 0; j < 8; j++)
#pragma unroll
                for (int r = 0; r < 4; r++) sc[j][r] = 0.f;

#pragma unroll
            for (int c = 0; c < 8; c++) {
                uint32_t abyte = (uint32_t)((wid * 16 + (lane & 15)) * AT_QSTR +
                                            c * 16 + (lane >> 4) * 8) * 2;
                uint32_t ah[4], al[4];
                ldm_x4(ah[0], ah[1], ah[2], ah[3], sbase + abyte);
                ldm_x4(al[0], al[1], al[2], al[3], sbase + AT_QPL + abyte);
                uint32_t b0h[8], b1h[8], b0l[8], b1l[8];
#pragma unroll
                for (int j2 = 0; j2 < 4; j2++) {
                    uint32_t bbyte = (uint32_t)((j2 * 16 + ((lane >> 4) & 1) * 8 + (lane & 7)) *
                                                    AT_KSTR + c * 16 + ((lane >> 3) & 1) * 8) * 2;
                    uint32_t r0, r1, r2, r3;
                    ldm_x4(r0, r1, r2, r3, sb + bbyte);
                    b0h[j2 * 2] = r0; b1h[j2 * 2] = r1; b0h[j2 * 2 + 1] = r2; b1h[j2 * 2 + 1] = r3;
                    ldm_x4(r0, r1, r2, r3, sb + AT_KPL + bbyte);
                    b0l[j2 * 2] = r0; b1l[j2 * 2] = r1; b0l[j2 * 2 + 1] = r2; b1l[j2 * 2 + 1] = r3;
                }
#pragma unroll
                for (int j = 0; j < 8; j++) {
                    mma_bf16(sc[j][0], sc[j][1], sc[j][2], sc[j][3],
                             ah[0], ah[1], ah[2], ah[3], b0h[j], b1h[j]);
                    mma_bf16(sc[j][0], sc[j][1], sc[j][2], sc[j][3],
                             ah[0], ah[1], ah[2], ah[3], b0l[j], b1l[j]);
                    mma_bf16(sc[j][0], sc[j][1], sc[j][2], sc[j][3],
                             al[0], al[1], al[2], al[3], b0h[j], b1h[j]);
                }
            }

            if (k0 + 63 > q0 + wid * 16) {
#pragma unroll
                for (int j = 0; j < 8; j++)
#pragma unroll
                    for (int r = 0; r < 4; r++) {
                        int col = k0 + j * 8 + t * 2 + (r & 1);
                        int row = q0 + wid * 16 + g + ((r >> 1) * 8);
                        if (col > row) sc[j][r] = -1e30f;
                    }
            }

            float mx0 = -1e30f, mx1 = -1e30f;
#pragma unroll
            for (int j = 0; j < 8; j++) {
                mx0 = fmaxf(mx0, fmaxf(sc[j][0], sc[j][1]));
                mx1 = fmaxf(mx1, fmaxf(sc[j][2], sc[j][3]));
            }
            mx0 = fmaxf(mx0, __shfl_xor_sync(0xffffffffu, mx0, 1));
            mx0 = fmaxf(mx0, __shfl_xor_sync(0xffffffffu, mx0, 2));
            mx1 = fmaxf(mx1, __shfl_xor_sync(0xffffffffu, mx1, 1));
            mx1 = fmaxf(mx1, __shfl_xor_sync(0xffffffffu, mx1, 2));
            float mn0 = fmaxf(mrow[0], mx0), mn1 = fmaxf(mrow[1], mx1);
            float cr0 = __expf(mrow[0] - mn0), cr1 = __expf(mrow[1] - mn1);
            mrow[0] = mn0; mrow[1] = mn1;
            float rs0 = 0.f, rs1 = 0.f;
#pragma unroll
            for (int j = 0; j < 8; j++) {
                sc[j][0] = __expf(sc[j][0] - mn0);
                sc[j][1] = __expf(sc[j][1] - mn0);
                sc[j][2] = __expf(sc[j][2] - mn1);
                sc[j][3] = __expf(sc[j][3] - mn1);
                rs0 += sc[j][0] + sc[j][1];
                rs1 += sc[j][2] + sc[j][3];
            }
            rs0 += __shfl_xor_sync(0xffffffffu, rs0, 1);
            rs0 += __shfl_xor_sync(0xffffffffu, rs0, 2);
            rs1 += __shfl_xor_sync(0xffffffffu, rs1, 1);
            rs1 += __shfl_xor_sync(0xffffffffu, rs1, 2);
            lrow[0] = lrow[0] * cr0 + rs0;
            lrow[1] = lrow[1] * cr1 + rs1;
#pragma unroll
            for (int n = 0; n < 16; n++) {
                o[n][0] *= cr0; o[n][1] *= cr0; o[n][2] *= cr1; o[n][3] *= cr1;
            }

            uint32_t pAh[8], pBh[8], pAl[8], pBl[8];
#pragma unroll
            for (int j = 0; j < 8; j++) {
                pAh[j] = pack_bf16(sc[j][0], sc[j][1]);
                pBh[j] = pack_bf16(sc[j][2], sc[j][3]);
                __nv_bfloat162 hA = *(__nv_bfloat162*)&pAh[j];
                __nv_bfloat162 hB = *(__nv_bfloat162*)&pBh[j];
                pAl[j] = pack_bf16(sc[j][0] - __bfloat162float(hA.x),
                                   sc[j][1] - __bfloat162float(hA.y));
                pBl[j] = pack_bf16(sc[j][2] - __bfloat162float(hB.x),
                                   sc[j][3] - __bfloat162float(hB.y));
            }

#pragma unroll
            for (int c = 0; c < 4; c++) {
                uint32_t vb0h[16], vb1h[16], vb0l[16], vb1l[16];
#pragma unroll
                for (int j2 = 0; j2 < 8; j2++) {
                    uint32_t bbyte = (uint32_t)((j2 * 16 + ((lane >> 4) & 1) * 8 + (lane & 7)) *
                                                    AT_VSTR + c * 16 + ((lane >> 3) & 1) * 8) * 2;
                    uint32_t r0, r1, r2, r3;
                    ldm_x4(r0, r1, r2, r3, sb + 2 * AT_KPL + bbyte);
                    vb0h[j2 * 2] = r0; vb1h[j2 * 2] = r1;
                    vb0h[j2 * 2 + 1] = r2; vb1h[j2 * 2 + 1] = r3;
                    ldm_x4(r0, r1, r2, r3, sb + 2 * AT_KPL + AT_VPL + bbyte);
                    vb0l[j2 * 2] = r0; vb1l[j2 * 2] = r1;
                    vb0l[j2 * 2 + 1] = r2; vb1l[j2 * 2 + 1] = r3;
                }
                uint32_t ah0 = pAh[2 * c], ah1 = pBh[2 * c], ah2 = pAh[2 * c + 1], ah3 = pBh[2 * c + 1];
                uint32_t al0 = pAl[2 * c], al1 = pBl[2 * c], al2 = pAl[2 * c + 1], al3 = pBl[2 * c + 1];
#pragma unroll
                for (int n = 0; n < 16; n++) {
                    mma_bf16(o[n][0], o[n][1], o[n][2], o[n][3],
                             ah0, ah1, ah2, ah3, vb0h[n], vb1h[n]);
                    mma_bf16(o[n][0], o[n][1], o[n][2], o[n][3],
                             ah0, ah1, ah2, ah3, vb0l[n], vb1l[n]);
                    mma_bf16(o[n][0], o[n][1], o[n][2], o[n][3],
                             al0, al1, al2, al3, vb0h[n], vb1h[n]);
                }
            }
        }
        __syncthreads();
        if (jt + 2 < ntiles) {
            load_kv(jt + 2, jt & 1);
            CP_COMMIT();
        }
    }

    float inv0 = 1.f / lrow[0], inv1 = 1.f / lrow[1];
    int row0 = q0 + wid * 16 + g;
#pragma unroll
    for (int n = 0; n < 16; n++) {
        int col = h * HDIM + n * 8 + t * 2;
        float v0 = o[n][0] * inv0, v1 = o[n][1] * inv0;
        float v2 = o[n][2] * inv1, v3 = o[n][3] * inv1;
        __nv_bfloat162 h01 = __floats2bfloat162_rn(v0, v1);
        __nv_bfloat162 l01 = __floats2bfloat162_rn(v0 - __bfloat162float(h01.x),
                                                   v1 - __bfloat162float(h01.y));
        __nv_bfloat162 h23 = __floats2bfloat162_rn(v2, v3);
        __nv_bfloat162 l23 = __floats2bfloat162_rn(v2 - __bfloat162float(h23.x),
                                                   v3 - __bfloat162float(h23.y));
        size_t p0 = (size_t)(b * S_LEN + row0) * DMODEL + col;
        size_t p1 = (size_t)(b * S_LEN + row0 + 8) * DMODEL + col;
        *(__nv_bfloat162*)&Ohi[p0] = h01;
        *(__nv_bfloat162*)&Olo[p0] = l01;
        *(__nv_bfloat162*)&Ohi[p1] = h23;
        *(__nv_bfloat162*)&Olo[p1] = l23;
    }
}

// ---------------------------------------------------------------------------
extern "C" void kernel_launch(void* const* d_in, const int* in_sizes, int n_in,
                              void* d_out, int out_size)
{
    const float* x  = (const float*)d_in[0];
    const float* wq = (const float*)d_in[1];
    const float* wk = (const float*)d_in[2];
    const float* wv = (const float*)d_in[3];
    const float* wo = (const float*)d_in[4];
    float* out = (float*)d_out;

    __nv_bfloat16 *xhi, *xlo, *whi, *wlo, *wohi, *wolo, *ohi, *olo;
    __nv_bfloat16 *qh, *ql, *kh, *kl, *vh, *vl;
    float *c;
    cudaGetSymbolAddress((void**)&xhi,  g_xhi);
    cudaGetSymbolAddress((void**)&xlo,  g_xlo);
    cudaGetSymbolAddress((void**)&whi,  g_whi);
    cudaGetSymbolAddress((void**)&wlo,  g_wlo);
    cudaGetSymbolAddress((void**)&wohi, g_wohi);
    cudaGetSymbolAddress((void**)&wolo, g_wolo);
    cudaGetSymbolAddress((void**)&ohi,  g_ohi);
    cudaGetSymbolAddress((void**)&olo,  g_olo);
    cudaGetSymbolAddress((void**)&c,  g_c);
    cudaGetSymbolAddress((void**)&qh, g_qh);
    cudaGetSymbolAddress((void**)&ql, g_ql);
    cudaGetSymbolAddress((void**)&kh, g_kh);
    cudaGetSymbolAddress((void**)&kl, g_kl);
    cudaGetSymbolAddress((void**)&vh, g_vh);
    cudaGetSymbolAddress((void**)&vl, g_vl);

    convert_split4<<<(MTOT * DMODEL / 4) / 256, 256>>>(
        (const float4*)x, (__nv_bfloat162*)xhi, (__nv_bfloat162*)xlo, MTOT * DMODEL / 4);
    convert_split4<<<(NH * HDIM * DMODEL / 4) / 256, 256>>>(
        (const float4*)wq, (__nv_bfloat162*)whi, (__nv_bfloat162*)wlo, NH * HDIM * DMODEL / 4);
    convert_split4<<<(NKV * HDIM * DMODEL / 4) / 256, 256>>>(
        (const float4*)wk, (__nv_bfloat162*)(whi + (size_t)NH * HDIM * DMODEL),
        (__nv_bfloat162*)(wlo + (size_t)NH * HDIM * DMODEL), NKV * HDIM * DMODEL / 4);
    convert_split4<<<(NKV * HDIM * DMODEL / 4) / 256, 256>>>(
        (const float4*)wv, (__nv_bfloat162*)(whi + (size_t)(NH + NKV) * HDIM * DMODEL),
        (__nv_bfloat162*)(wlo + (size_t)(NH + NKV) * HDIM * DMODEL), NKV * HDIM * DMODEL / 4);
    convert_split4<<<(DMODEL * DMODEL / 4) / 256, 256>>>(
        (const float4*)wo, (__nv_bfloat162*)wohi, (__nv_bfloat162*)wolo, DMODEL * DMODEL / 4);

    cudaFuncSetAttribute(hmma_gemm_fused, cudaFuncAttributeMaxDynamicSharedMemorySize, FG_SMEM);

    // fused QKV projection: C[4096, 3072]
    hmma_gemm_fused<<<dim3(NQKV / 128, MTOT / 128), 256, FG_SMEM>>>(xhi, xlo, whi, wlo, c, NQKV);

    rope_qk<<<(QCOUNT + KCOUNT) / 256, 256>>>(c, qh, ql, kh, kl);
    v_tr<<<dim3(S_LEN / 32, HDIM / 32, B_SZ * NKV), 256>>>(c, vh, vl);

    cudaFuncSetAttribute(attn_mma, cudaFuncAttributeMaxDynamicSharedMemorySize, AT_SM);
    attn_mma<<<dim3(S_LEN / 128, B_SZ * NH), 256, AT_SM>>>(qh, ql, kh, kl, vh, vl, ohi, olo);

    hmma_gemm_fused<<<dim3(DMODEL / 128, MTOT / 128), 256, FG_SMEM>>>(ohi, olo, wohi, wolo, out, DMODEL);
}